// round 6
// baseline (speedup 1.0000x reference)
#include <cuda_runtime.h>
#include <cuda_fp16.h>

// ContinuousEmbedding via trig factorization + fp16 tables + dynamic queue:
//   w_j = 0.5 + 0.5*cos(a)cos(j*pi/4) + 0.5*sin(a)sin(j*pi/4), a=(pi/4)(t+3)
//   out[x] = c0*A0[pbi] + c1*A1[pbi] + c2*A2[pbi]   (coeffs fp32)
// A0/A1/A2 per-block in shared as __half (zero-masked rows outside grid ->
// exact boundary handling). Per x: 1 broadcast LDS.128 + 3 LDS.64 + STG.128.
// R5: atomic tile queue (kills the 2-vs-3-tile straggler tail) + unrolled
// full-tile fast path for ILP.

#define NUM_POINTS 64
#define OUT_DIMS   128
#define V4_PER_ROW (OUT_DIMS / 4)     // 32
#define NPBI       65                 // pbi = pb+3 in [0,64]
#define ROW_BYTES  256                // 128 dims * 2B fp16
#define PBI_STRIDE 768                // 3 tables * 256B
#define TBL_BYTES  (NPBI * PBI_STRIDE)        // 49,920
#define WARPS_PB   16                 // 512 threads
#define STAGE_BYTES (WARPS_PB * 32 * 16)      // 8,192
#define SMEM_BYTES (TBL_BYTES + STAGE_BYTES)  // 58,112
#define RSQ2       0.70710678118654752440f
#define BLOCK      512
#define TPG        2                  // tiles per atomic grab (64 x)

__device__ unsigned int g_tile_ctr;

__global__ void ce_reset_ctr() { g_tile_ctr = 0u; }

extern __shared__ unsigned char s_raw[];

__device__ __forceinline__ float2 h2f(unsigned int u) {
    __half2 h = *reinterpret_cast<__half2*>(&u);
    return __half22float2(h);
}

__global__ __launch_bounds__(BLOCK, 3)
void ContinuousEmbedding_89412629168402_kernel(const float* __restrict__ x,
                                               const float* __restrict__ emb,
                                               float* __restrict__ out,
                                               int n_x)
{
    // ---- build fp16 A0/A1/A2 tables (once per block) ----
    const float4* __restrict__ emb4 = reinterpret_cast<const float4*>(emb);
    {
        const float cj[8] = {1.f,  RSQ2, 0.f, -RSQ2, -1.f, -RSQ2,  0.f,  RSQ2};
        const float sj[8] = {0.f,  RSQ2, 1.f,  RSQ2,  0.f, -RSQ2, -1.f, -RSQ2};
        for (int tr = threadIdx.x; tr < NPBI * V4_PER_ROW; tr += BLOCK) {
            const int pbi = tr >> 5;
            const int ch  = tr & 31;
            const int pb  = pbi - 3;
            float4 a0 = make_float4(0.f,0.f,0.f,0.f);
            float4 a1 = a0, a2 = a0;
            #pragma unroll
            for (int j = 0; j < 8; ++j) {
                const int p = pb + j;
                if (p >= 0 && p < NUM_POINTS) {
                    const float4 e = __ldg(&emb4[p * V4_PER_ROW + ch]);
                    a0.x += e.x; a0.y += e.y; a0.z += e.z; a0.w += e.w;
                    a1.x = fmaf(cj[j], e.x, a1.x); a1.y = fmaf(cj[j], e.y, a1.y);
                    a1.z = fmaf(cj[j], e.z, a1.z); a1.w = fmaf(cj[j], e.w, a1.w);
                    a2.x = fmaf(sj[j], e.x, a2.x); a2.y = fmaf(sj[j], e.y, a2.y);
                    a2.z = fmaf(sj[j], e.z, a2.z); a2.w = fmaf(sj[j], e.w, a2.w);
                }
            }
            unsigned char* base = s_raw + pbi * PBI_STRIDE + ch * 8;
            __half2* d0 = reinterpret_cast<__half2*>(base);
            __half2* d1 = reinterpret_cast<__half2*>(base + ROW_BYTES);
            __half2* d2 = reinterpret_cast<__half2*>(base + 2 * ROW_BYTES);
            d0[0] = __floats2half2_rn(a0.x, a0.y);
            d0[1] = __floats2half2_rn(a0.z, a0.w);
            d1[0] = __floats2half2_rn(a1.x, a1.y);
            d1[1] = __floats2half2_rn(a1.z, a1.w);
            d2[0] = __floats2half2_rn(a2.x, a2.y);
            d2[1] = __floats2half2_rn(a2.z, a2.w);
        }
    }
    __syncthreads();

    const int lane = threadIdx.x & 31;
    const int wl   = threadIdx.x >> 5;
    const int n_tiles = (n_x + 31) >> 5;
    const unsigned int n_grabs = (unsigned int)((n_tiles + TPG - 1) / TPG);

    float4* stage = reinterpret_cast<float4*>(s_raw + TBL_BYTES) + wl * 32;
    float4* __restrict__ out4 = reinterpret_cast<float4*>(out);

    const float cj[8] = {1.f,  RSQ2, 0.f, -RSQ2, -1.f, -RSQ2,  0.f,  RSQ2};
    const float sj[8] = {0.f,  RSQ2, 1.f,  RSQ2,  0.f, -RSQ2, -1.f, -RSQ2};

    for (;;) {
        // ---- grab TPG tiles from the global queue ----
        unsigned int grab = 0;
        if (lane == 0) grab = atomicAdd(&g_tile_ctr, 1u);
        grab = __shfl_sync(0xffffffffu, grab, 0);
        if (grab >= n_grabs) break;

        #pragma unroll
        for (int sub = 0; sub < TPG; ++sub) {
            const int wt = (int)grab * TPG + sub;
            if (wt >= n_tiles) break;
            const int base = wt << 5;

            // ---- per-lane precompute for this lane's x ----
            const int xi = base + lane;
            const float xv = (xi < n_x) ? x[xi] : 0.f;
            const float xs = (xv + 1.0f) * 32.0f;
            const float f  = floorf(xs);
            const int   pb = (int)f - 3;
            const float t  = xs - f;
            const float a  = 0.78539816339744830962f * (t + 3.0f);
            const float ca = __cosf(a);
            const float sa = __sinf(a);

            float n0 = 0.f, n1 = 0.f, n2 = 0.f;
            #pragma unroll
            for (int j = 0; j < 8; ++j) {
                const int p = pb + j;
                if (p >= 0 && p < NUM_POINTS) { n0 += 1.f; n1 += cj[j]; n2 += sj[j]; }
            }
            const float s   = 0.5f * (n0 + ca * n1 + sa * n2);
            const float inv = (s > 0.f) ? (1.0f / s) : 0.f;
            int pbi = pb + 3;
            pbi = max(0, min(NPBI - 1, pbi));

            float4 cf;
            cf.x = 0.5f * inv;
            cf.y = 0.5f * ca * inv;
            cf.z = 0.5f * sa * inv;
            cf.w = __int_as_float(pbi * PBI_STRIDE);

            __syncwarp();
            stage[lane] = cf;
            __syncwarp();

            const int cnt = min(32, n_x - base);
            if (cnt == 32) {
                #pragma unroll 4
                for (int k = 0; k < 32; ++k) {
                    const float4 c = stage[k];          // broadcast LDS.128
                    const unsigned char* row =
                        s_raw + __float_as_int(c.w) + lane * 8;
                    const uint2 u0 = *reinterpret_cast<const uint2*>(row);
                    const uint2 u1 = *reinterpret_cast<const uint2*>(row + ROW_BYTES);
                    const uint2 u2 = *reinterpret_cast<const uint2*>(row + 2 * ROW_BYTES);

                    const float2 a0l = h2f(u0.x), a0h = h2f(u0.y);
                    const float2 a1l = h2f(u1.x), a1h = h2f(u1.y);
                    const float2 a2l = h2f(u2.x), a2h = h2f(u2.y);

                    float4 acc;
                    acc.x = fmaf(c.z, a2l.x, fmaf(c.y, a1l.x, c.x * a0l.x));
                    acc.y = fmaf(c.z, a2l.y, fmaf(c.y, a1l.y, c.x * a0l.y));
                    acc.z = fmaf(c.z, a2h.x, fmaf(c.y, a1h.x, c.x * a0h.x));
                    acc.w = fmaf(c.z, a2h.y, fmaf(c.y, a1h.y, c.x * a0h.y));

                    __stcs(&out4[(size_t)(base + k) * V4_PER_ROW + lane], acc);
                }
            } else {
                for (int k = 0; k < cnt; ++k) {
                    const float4 c = stage[k];
                    const unsigned char* row =
                        s_raw + __float_as_int(c.w) + lane * 8;
                    const uint2 u0 = *reinterpret_cast<const uint2*>(row);
                    const uint2 u1 = *reinterpret_cast<const uint2*>(row + ROW_BYTES);
                    const uint2 u2 = *reinterpret_cast<const uint2*>(row + 2 * ROW_BYTES);

                    const float2 a0l = h2f(u0.x), a0h = h2f(u0.y);
                    const float2 a1l = h2f(u1.x), a1h = h2f(u1.y);
                    const float2 a2l = h2f(u2.x), a2h = h2f(u2.y);

                    float4 acc;
                    acc.x = fmaf(c.z, a2l.x, fmaf(c.y, a1l.x, c.x * a0l.x));
                    acc.y = fmaf(c.z, a2l.y, fmaf(c.y, a1l.y, c.x * a0l.y));
                    acc.z = fmaf(c.z, a2h.x, fmaf(c.y, a1h.x, c.x * a0h.x));
                    acc.w = fmaf(c.z, a2h.y, fmaf(c.y, a1h.y, c.x * a0h.y));

                    __stcs(&out4[(size_t)(base + k) * V4_PER_ROW + lane], acc);
                }
            }
        }
    }
}

extern "C" void kernel_launch(void* const* d_in, const int* in_sizes, int n_in,
                              void* d_out, int out_size)
{
    const float* x   = (const float*)d_in[0];   // [64, 8192] f32
    const float* emb = (const float*)d_in[1];   // [64, 128]  f32
    float* out = (float*)d_out;                 // [64, 8192, 128] f32

    const int n_x = in_sizes[0];                // 524288

    static bool attr_set = false;
    if (!attr_set) {
        cudaFuncSetAttribute(ContinuousEmbedding_89412629168402_kernel,
                             cudaFuncAttributeMaxDynamicSharedMemorySize,
                             SMEM_BYTES);
        attr_set = true;
    }

    ce_reset_ctr<<<1, 1>>>();
    // 3 CTAs/SM * ~152 SMs, persistent warps pulling from the tile queue
    const int blocks = 456;
    ContinuousEmbedding_89412629168402_kernel<<<blocks, BLOCK, SMEM_BYTES>>>(
        x, emb, out, n_x);
}

// round 7
// speedup vs baseline: 1.0084x; 1.0084x over previous
#include <cuda_runtime.h>
#include <cuda_fp16.h>

// ContinuousEmbedding via trig factorization + fp16 tables:
//   w_j = 0.5 + 0.5*cos(a)cos(j*pi/4) + 0.5*sin(a)sin(j*pi/4), a=(pi/4)(t+3)
//   out[x] = c0*A0[pbi] + c1*A1[pbi] + c2*A2[pbi]   (coeffs fp32)
// A0/A1/A2 per-block in shared as __half (zero-masked rows outside grid ->
// exact boundary handling). Per x: 1 broadcast LDS.128 + 3 LDS.64 + STG.128.
//
// R6: revert R5's atomic queue (regressed: single-address L2 atomic
// serialization). NPBI 65->64 + launch_bounds(512,4) -> 4 CTAs/SM,
// 64 warps/SM to cover the LDS->cvt->FMA latency chain.

#define NUM_POINTS 64
#define OUT_DIMS   128
#define V4_PER_ROW (OUT_DIMS / 4)     // 32
#define NPBI       64                 // pbi = pb+3 in [0,63] (pb in [-3,60])
#define ROW_BYTES  256                // 128 dims * 2B fp16
#define PBI_STRIDE 768                // 3 tables * 256B
#define TBL_BYTES  (NPBI * PBI_STRIDE)        // 49,152
#define WARPS_PB   16                 // 512 threads
#define STAGE_BYTES (WARPS_PB * 32 * 16)      // 8,192
#define SMEM_BYTES (TBL_BYTES + STAGE_BYTES)  // 57,344 -> 4 CTAs/SM
#define RSQ2       0.70710678118654752440f
#define BLOCK      512

extern __shared__ unsigned char s_raw[];

__device__ __forceinline__ float2 h2f(unsigned int u) {
    __half2 h = *reinterpret_cast<__half2*>(&u);
    return __half22float2(h);
}

__global__ __launch_bounds__(BLOCK, 4)
void ContinuousEmbedding_89412629168402_kernel(const float* __restrict__ x,
                                               const float* __restrict__ emb,
                                               float* __restrict__ out,
                                               int n_x)
{
    // ---- build fp16 A0/A1/A2 tables (once per block) ----
    const float4* __restrict__ emb4 = reinterpret_cast<const float4*>(emb);
    {
        const float cj[8] = {1.f,  RSQ2, 0.f, -RSQ2, -1.f, -RSQ2,  0.f,  RSQ2};
        const float sj[8] = {0.f,  RSQ2, 1.f,  RSQ2,  0.f, -RSQ2, -1.f, -RSQ2};
        for (int tr = threadIdx.x; tr < NPBI * V4_PER_ROW; tr += BLOCK) {
            const int pbi = tr >> 5;
            const int ch  = tr & 31;
            const int pb  = pbi - 3;
            float4 a0 = make_float4(0.f,0.f,0.f,0.f);
            float4 a1 = a0, a2 = a0;
            #pragma unroll
            for (int j = 0; j < 8; ++j) {
                const int p = pb + j;
                if (p >= 0 && p < NUM_POINTS) {
                    const float4 e = __ldg(&emb4[p * V4_PER_ROW + ch]);
                    a0.x += e.x; a0.y += e.y; a0.z += e.z; a0.w += e.w;
                    a1.x = fmaf(cj[j], e.x, a1.x); a1.y = fmaf(cj[j], e.y, a1.y);
                    a1.z = fmaf(cj[j], e.z, a1.z); a1.w = fmaf(cj[j], e.w, a1.w);
                    a2.x = fmaf(sj[j], e.x, a2.x); a2.y = fmaf(sj[j], e.y, a2.y);
                    a2.z = fmaf(sj[j], e.z, a2.z); a2.w = fmaf(sj[j], e.w, a2.w);
                }
            }
            unsigned char* base = s_raw + pbi * PBI_STRIDE + ch * 8;
            __half2* d0 = reinterpret_cast<__half2*>(base);
            __half2* d1 = reinterpret_cast<__half2*>(base + ROW_BYTES);
            __half2* d2 = reinterpret_cast<__half2*>(base + 2 * ROW_BYTES);
            d0[0] = __floats2half2_rn(a0.x, a0.y);
            d0[1] = __floats2half2_rn(a0.z, a0.w);
            d1[0] = __floats2half2_rn(a1.x, a1.y);
            d1[1] = __floats2half2_rn(a1.z, a1.w);
            d2[0] = __floats2half2_rn(a2.x, a2.y);
            d2[1] = __floats2half2_rn(a2.z, a2.w);
        }
    }
    __syncthreads();

    const int lane    = threadIdx.x & 31;
    const int wl      = threadIdx.x >> 5;
    const int wid_g   = blockIdx.x * WARPS_PB + wl;
    const int w_total = gridDim.x * WARPS_PB;
    const int n_tiles = (n_x + 31) >> 5;

    float4* stage = reinterpret_cast<float4*>(s_raw + TBL_BYTES) + wl * 32;
    float4* __restrict__ out4 = reinterpret_cast<float4*>(out);

    const float cj[8] = {1.f,  RSQ2, 0.f, -RSQ2, -1.f, -RSQ2,  0.f,  RSQ2};
    const float sj[8] = {0.f,  RSQ2, 1.f,  RSQ2,  0.f, -RSQ2, -1.f, -RSQ2};

    for (int wt = wid_g; wt < n_tiles; wt += w_total) {
        const int base = wt << 5;

        // ---- per-lane precompute for this lane's x ----
        const int xi = base + lane;
        const float xv = (xi < n_x) ? x[xi] : 0.f;
        const float xs = (xv + 1.0f) * 32.0f;
        const float f  = floorf(xs);
        const int   pb = (int)f - 3;
        const float t  = xs - f;
        const float a  = 0.78539816339744830962f * (t + 3.0f);
        const float ca = __cosf(a);
        const float sa = __sinf(a);

        float n0 = 0.f, n1 = 0.f, n2 = 0.f;
        #pragma unroll
        for (int j = 0; j < 8; ++j) {
            const int p = pb + j;
            if (p >= 0 && p < NUM_POINTS) { n0 += 1.f; n1 += cj[j]; n2 += sj[j]; }
        }
        const float s   = 0.5f * (n0 + ca * n1 + sa * n2);
        const float inv = (s > 0.f) ? (1.0f / s) : 0.f;
        int pbi = pb + 3;
        pbi = max(0, min(NPBI - 1, pbi));

        float4 cf;
        cf.x = 0.5f * inv;
        cf.y = 0.5f * ca * inv;
        cf.z = 0.5f * sa * inv;
        cf.w = __int_as_float(pbi * PBI_STRIDE);

        __syncwarp();                 // previous tile's readers are done
        stage[lane] = cf;
        __syncwarp();                 // staging visible to all lanes

        // ---- broadcast loop: one x per k ----
        const int cnt = min(32, n_x - base);
        for (int k = 0; k < cnt; ++k) {
            const float4 c = stage[k];               // broadcast LDS.128
            const unsigned char* row = s_raw + __float_as_int(c.w) + lane * 8;
            const uint2 u0 = *reinterpret_cast<const uint2*>(row);
            const uint2 u1 = *reinterpret_cast<const uint2*>(row + ROW_BYTES);
            const uint2 u2 = *reinterpret_cast<const uint2*>(row + 2 * ROW_BYTES);

            const float2 a0l = h2f(u0.x), a0h = h2f(u0.y);
            const float2 a1l = h2f(u1.x), a1h = h2f(u1.y);
            const float2 a2l = h2f(u2.x), a2h = h2f(u2.y);

            float4 acc;
            acc.x = fmaf(c.z, a2l.x, fmaf(c.y, a1l.x, c.x * a0l.x));
            acc.y = fmaf(c.z, a2l.y, fmaf(c.y, a1l.y, c.x * a0l.y));
            acc.z = fmaf(c.z, a2h.x, fmaf(c.y, a1h.x, c.x * a0h.x));
            acc.w = fmaf(c.z, a2h.y, fmaf(c.y, a1h.y, c.x * a0h.y));

            __stcs(&out4[(size_t)(base + k) * V4_PER_ROW + lane], acc);
        }
    }
}

extern "C" void kernel_launch(void* const* d_in, const int* in_sizes, int n_in,
                              void* d_out, int out_size)
{
    const float* x   = (const float*)d_in[0];   // [64, 8192] f32
    const float* emb = (const float*)d_in[1];   // [64, 128]  f32
    float* out = (float*)d_out;                 // [64, 8192, 128] f32

    const int n_x = in_sizes[0];                // 524288

    static bool attr_set = false;
    if (!attr_set) {
        cudaFuncSetAttribute(ContinuousEmbedding_89412629168402_kernel,
                             cudaFuncAttributeMaxDynamicSharedMemorySize,
                             SMEM_BYTES);
        attr_set = true;
    }

    // 4 CTAs/SM * 152 SMs, grid-stride over 32-x tiles
    const int blocks = 608;
    ContinuousEmbedding_89412629168402_kernel<<<blocks, BLOCK, SMEM_BYTES>>>(
        x, emb, out, n_x);
}

// round 8
// speedup vs baseline: 1.0871x; 1.0780x over previous
#include <cuda_runtime.h>
#include <cuda_fp16.h>

// ContinuousEmbedding via trig factorization + fp16 tables + half2 combine:
//   w_j = 0.5 + 0.5*cos(a)cos(j*pi/4) + 0.5*sin(a)sin(j*pi/4), a=(pi/4)(t+3)
//   out[x] = c0*A0[pbi] + c1*A1[pbi] + c2*A2[pbi]
// A0/A1/A2 per-block in shared as __half (zero-masked rows outside grid ->
// exact boundary handling).
//
// R7: combine in half2 (HMUL2/HFMA2), convert only the 4 result values to
// fp32 (4 F2F/x instead of 12) -> removes the convert-pipe bottleneck.
// Config reverted to the verified-best R4 shape: 3 CTAs/SM, static grid 456.

#define NUM_POINTS 64
#define OUT_DIMS   128
#define V4_PER_ROW (OUT_DIMS / 4)     // 32
#define NPBI       64                 // pbi = pb+3 in [0,63] (pb in [-3,60])
#define ROW_BYTES  256                // 128 dims * 2B fp16
#define PBI_STRIDE 768                // 3 tables * 256B
#define TBL_BYTES  (NPBI * PBI_STRIDE)        // 49,152
#define WARPS_PB   16                 // 512 threads
#define STAGE_BYTES (WARPS_PB * 32 * 16)      // 8,192
#define SMEM_BYTES (TBL_BYTES + STAGE_BYTES)  // 57,344
#define RSQ2       0.70710678118654752440f
#define BLOCK      512

extern __shared__ unsigned char s_raw[];

__global__ __launch_bounds__(BLOCK, 3)
void ContinuousEmbedding_89412629168402_kernel(const float* __restrict__ x,
                                               const float* __restrict__ emb,
                                               float* __restrict__ out,
                                               int n_x)
{
    // ---- build fp16 A0/A1/A2 tables (once per block) ----
    const float4* __restrict__ emb4 = reinterpret_cast<const float4*>(emb);
    {
        const float cj[8] = {1.f,  RSQ2, 0.f, -RSQ2, -1.f, -RSQ2,  0.f,  RSQ2};
        const float sj[8] = {0.f,  RSQ2, 1.f,  RSQ2,  0.f, -RSQ2, -1.f, -RSQ2};
        for (int tr = threadIdx.x; tr < NPBI * V4_PER_ROW; tr += BLOCK) {
            const int pbi = tr >> 5;
            const int ch  = tr & 31;
            const int pb  = pbi - 3;
            float4 a0 = make_float4(0.f,0.f,0.f,0.f);
            float4 a1 = a0, a2 = a0;
            #pragma unroll
            for (int j = 0; j < 8; ++j) {
                const int p = pb + j;
                if (p >= 0 && p < NUM_POINTS) {
                    const float4 e = __ldg(&emb4[p * V4_PER_ROW + ch]);
                    a0.x += e.x; a0.y += e.y; a0.z += e.z; a0.w += e.w;
                    a1.x = fmaf(cj[j], e.x, a1.x); a1.y = fmaf(cj[j], e.y, a1.y);
                    a1.z = fmaf(cj[j], e.z, a1.z); a1.w = fmaf(cj[j], e.w, a1.w);
                    a2.x = fmaf(sj[j], e.x, a2.x); a2.y = fmaf(sj[j], e.y, a2.y);
                    a2.z = fmaf(sj[j], e.z, a2.z); a2.w = fmaf(sj[j], e.w, a2.w);
                }
            }
            unsigned char* base = s_raw + pbi * PBI_STRIDE + ch * 8;
            __half2* d0 = reinterpret_cast<__half2*>(base);
            __half2* d1 = reinterpret_cast<__half2*>(base + ROW_BYTES);
            __half2* d2 = reinterpret_cast<__half2*>(base + 2 * ROW_BYTES);
            d0[0] = __floats2half2_rn(a0.x, a0.y);
            d0[1] = __floats2half2_rn(a0.z, a0.w);
            d1[0] = __floats2half2_rn(a1.x, a1.y);
            d1[1] = __floats2half2_rn(a1.z, a1.w);
            d2[0] = __floats2half2_rn(a2.x, a2.y);
            d2[1] = __floats2half2_rn(a2.z, a2.w);
        }
    }
    __syncthreads();

    const int lane    = threadIdx.x & 31;
    const int wl      = threadIdx.x >> 5;
    const int wid_g   = blockIdx.x * WARPS_PB + wl;
    const int w_total = gridDim.x * WARPS_PB;
    const int n_tiles = (n_x + 31) >> 5;

    float4* stage = reinterpret_cast<float4*>(s_raw + TBL_BYTES) + wl * 32;
    float4* __restrict__ out4 = reinterpret_cast<float4*>(out);

    const float cj[8] = {1.f,  RSQ2, 0.f, -RSQ2, -1.f, -RSQ2,  0.f,  RSQ2};
    const float sj[8] = {0.f,  RSQ2, 1.f,  RSQ2,  0.f, -RSQ2, -1.f, -RSQ2};

    for (int wt = wid_g; wt < n_tiles; wt += w_total) {
        const int base = wt << 5;

        // ---- per-lane precompute for this lane's x ----
        const int xi = base + lane;
        const float xv = (xi < n_x) ? x[xi] : 0.f;
        const float xs = (xv + 1.0f) * 32.0f;
        const float f  = floorf(xs);
        const int   pb = (int)f - 3;
        const float t  = xs - f;
        const float a  = 0.78539816339744830962f * (t + 3.0f);
        const float ca = __cosf(a);
        const float sa = __sinf(a);

        float n0 = 0.f, n1 = 0.f, n2 = 0.f;
        #pragma unroll
        for (int j = 0; j < 8; ++j) {
            const int p = pb + j;
            if (p >= 0 && p < NUM_POINTS) { n0 += 1.f; n1 += cj[j]; n2 += sj[j]; }
        }
        const float s   = 0.5f * (n0 + ca * n1 + sa * n2);
        const float inv = (s > 0.f) ? (1.0f / s) : 0.f;
        int pbi = pb + 3;
        pbi = max(0, min(NPBI - 1, pbi));

        // coeffs as duplicated half2 (bits stashed in float4 stage)
        const __half2 h0 = __float2half2_rn(0.5f * inv);
        const __half2 h1 = __float2half2_rn(0.5f * ca * inv);
        const __half2 h2c = __float2half2_rn(0.5f * sa * inv);

        float4 cf;
        cf.x = __uint_as_float(*reinterpret_cast<const unsigned int*>(&h0));
        cf.y = __uint_as_float(*reinterpret_cast<const unsigned int*>(&h1));
        cf.z = __uint_as_float(*reinterpret_cast<const unsigned int*>(&h2c));
        cf.w = __int_as_float(pbi * PBI_STRIDE);

        __syncwarp();                 // previous tile's readers are done
        stage[lane] = cf;
        __syncwarp();                 // staging visible to all lanes

        // ---- broadcast loop: one x per k ----
        const int cnt = min(32, n_x - base);
        for (int k = 0; k < cnt; ++k) {
            const float4 c = stage[k];               // broadcast LDS.128
            const unsigned int b0 = __float_as_uint(c.x);
            const unsigned int b1 = __float_as_uint(c.y);
            const unsigned int b2 = __float_as_uint(c.z);
            const __half2 C0 = *reinterpret_cast<const __half2*>(&b0);
            const __half2 C1 = *reinterpret_cast<const __half2*>(&b1);
            const __half2 C2 = *reinterpret_cast<const __half2*>(&b2);

            const unsigned char* row = s_raw + __float_as_int(c.w) + lane * 8;
            const uint2 u0 = *reinterpret_cast<const uint2*>(row);
            const uint2 u1 = *reinterpret_cast<const uint2*>(row + ROW_BYTES);
            const uint2 u2 = *reinterpret_cast<const uint2*>(row + 2 * ROW_BYTES);

            const __half2 A0l = *reinterpret_cast<const __half2*>(&u0.x);
            const __half2 A0h = *reinterpret_cast<const __half2*>(&u0.y);
            const __half2 A1l = *reinterpret_cast<const __half2*>(&u1.x);
            const __half2 A1h = *reinterpret_cast<const __half2*>(&u1.y);
            const __half2 A2l = *reinterpret_cast<const __half2*>(&u2.x);
            const __half2 A2h = *reinterpret_cast<const __half2*>(&u2.y);

            const __half2 accl = __hfma2(A2l, C2, __hfma2(A1l, C1, __hmul2(A0l, C0)));
            const __half2 acch = __hfma2(A2h, C2, __hfma2(A1h, C1, __hmul2(A0h, C0)));

            const float2 lo = __half22float2(accl);
            const float2 hi = __half22float2(acch);
            float4 acc;
            acc.x = lo.x; acc.y = lo.y; acc.z = hi.x; acc.w = hi.y;

            __stcs(&out4[(size_t)(base + k) * V4_PER_ROW + lane], acc);
        }
    }
}

extern "C" void kernel_launch(void* const* d_in, const int* in_sizes, int n_in,
                              void* d_out, int out_size)
{
    const float* x   = (const float*)d_in[0];   // [64, 8192] f32
    const float* emb = (const float*)d_in[1];   // [64, 128]  f32
    float* out = (float*)d_out;                 // [64, 8192, 128] f32

    const int n_x = in_sizes[0];                // 524288

    static bool attr_set = false;
    if (!attr_set) {
        cudaFuncSetAttribute(ContinuousEmbedding_89412629168402_kernel,
                             cudaFuncAttributeMaxDynamicSharedMemorySize,
                             SMEM_BYTES);
        attr_set = true;
    }

    // 3 CTAs/SM * ~152 SMs, grid-stride over 32-x tiles (verified-best config)
    const int blocks = 456;
    ContinuousEmbedding_89412629168402_kernel<<<blocks, BLOCK, SMEM_BYTES>>>(
        x, emb, out, n_x);
}